// round 2
// baseline (speedup 1.0000x reference)
#include <cuda_runtime.h>
#include <math.h>

// Problem constants
#define Bn 4
#define Tn 2048
#define Dn 1024
#define Hn 16
#define Kd 64
#define HK 1024   // Hn*Kd

typedef unsigned long long u64;

// ---- packed f32x2 helpers (B300 FFMA2 path; 2x fp32 throughput vs FFMA-3reg) ----
__device__ __forceinline__ void fma2(u64 &d, u64 a, u64 b) {
    asm("fma.rn.f32x2 %0, %1, %2, %0;" : "+l"(d) : "l"(a), "l"(b));
}
__device__ __forceinline__ u64 mul2(u64 a, u64 b) {
    u64 r; asm("mul.rn.f32x2 %0, %1, %2;" : "=l"(r) : "l"(a), "l"(b)); return r;
}
__device__ __forceinline__ u64 dup2(float x) {
    u64 r; asm("mov.b64 %0, {%1, %1};" : "=l"(r) : "f"(x)); return r;
}
__device__ __forceinline__ float sum2(u64 v) {
    float lo, hi; asm("mov.b64 {%0, %1}, %2;" : "=f"(lo), "=f"(hi) : "l"(v));
    return lo + hi;
}

// Scratch (device globals; no cudaMalloc allowed)
__device__ float g_q[Bn * Hn * Tn * Kd];
__device__ float g_k[Bn * Hn * Tn * Kd];
__device__ float g_v[Bn * Hn * Tn * Kd];
__device__ float g_ao[Bn * Tn * HK];

// ---------------------------------------------------------------------------
// Kernel 1: QKV projections. Block tile 128(m) x 64(n), k-chunk 32.
// Micro-tile 8x4 per thread, f32x2 FMAs with pairs along k.
// A (X rows) kept natural [m][k] in smem (compute loads are broadcasts).
// W transposed into Bs[n][k] with XOR swizzle on k.
// ---------------------------------------------------------------------------
__global__ __launch_bounds__(256, 2) void qkv_kernel(
    const float* __restrict__ X,
    const float* __restrict__ Wq,
    const float* __restrict__ Wk,
    const float* __restrict__ Wv)
{
    __shared__ float As[128][36];
    __shared__ float Bs[64][36];

    const int mblk  = blockIdx.x;   // 0..T/128-1
    const int bh    = blockIdx.y;   // 0..B*H-1
    const int which = blockIdx.z;   // 0:q 1:k 2:v

    const int b = bh >> 4;
    const int h = bh & 15;

    const float* W = ((which == 0) ? Wq : (which == 1) ? Wk : Wv) + (size_t)h * Dn * Kd;
    const float* A = X + (size_t)b * Tn * Dn + (size_t)mblk * 128 * Dn;
    float* out = ((which == 0) ? g_q : (which == 1) ? g_k : g_v)
               + ((size_t)bh * Tn + (size_t)mblk * 128) * Kd;

    const int tid = threadIdx.x;
    const int tx = tid & 15, ty = tid >> 4;
    const int a_m = tid >> 1, a_k = (tid & 1) << 4;   // A tile 128x32, 16 floats/thread
    const int w_k = tid >> 3, w_n = (tid & 7) << 3;   // W tile 32x64, 8 floats/thread

    u64 acc[8][4];
#pragma unroll
    for (int i = 0; i < 8; i++)
#pragma unroll
        for (int j = 0; j < 4; j++) acc[i][j] = 0ull;

    for (int kk = 0; kk < Dn; kk += 32) {
        float4 a0 = *(const float4*)(A + (size_t)a_m * Dn + kk + a_k + 0);
        float4 a1 = *(const float4*)(A + (size_t)a_m * Dn + kk + a_k + 4);
        float4 a2 = *(const float4*)(A + (size_t)a_m * Dn + kk + a_k + 8);
        float4 a3 = *(const float4*)(A + (size_t)a_m * Dn + kk + a_k + 12);
        float4 w0 = *(const float4*)(W + (size_t)(kk + w_k) * Kd + w_n + 0);
        float4 w1 = *(const float4*)(W + (size_t)(kk + w_k) * Kd + w_n + 4);
        __syncthreads();
        *(float4*)&As[a_m][a_k + 0]  = a0;
        *(float4*)&As[a_m][a_k + 4]  = a1;
        *(float4*)&As[a_m][a_k + 8]  = a2;
        *(float4*)&As[a_m][a_k + 12] = a3;
        {
            float wv[8] = {w0.x, w0.y, w0.z, w0.w, w1.x, w1.y, w1.z, w1.w};
#pragma unroll
            for (int c = 0; c < 8; c++) {
                int n = w_n + c;
                Bs[n][w_k ^ (((n >> 2) & 7) << 2)] = wv[c];
            }
        }
        __syncthreads();
#pragma unroll
        for (int k4 = 0; k4 < 32; k4 += 4) {
            u64 bx[4], by[4];
#pragma unroll
            for (int j = 0; j < 4; j++) {
                int n = tx + 16 * j;
                ulonglong2 t = *(const ulonglong2*)&Bs[n][k4 ^ (((n >> 2) & 7) << 2)];
                bx[j] = t.x; by[j] = t.y;
            }
#pragma unroll
            for (int i = 0; i < 8; i++) {
                ulonglong2 aa = *(const ulonglong2*)&As[ty * 8 + i][k4];
#pragma unroll
                for (int j = 0; j < 4; j++) {
                    fma2(acc[i][j], aa.x, bx[j]);
                    fma2(acc[i][j], aa.y, by[j]);
                }
            }
        }
    }
#pragma unroll
    for (int i = 0; i < 8; i++)
#pragma unroll
        for (int j = 0; j < 4; j++)
            out[(size_t)(ty * 8 + i) * Kd + tx + 16 * j] = sum2(acc[i][j]);
}

// ---------------------------------------------------------------------------
// Kernel 2: causal flash attention, 64q x 64k tiles, 256 threads, 4x4 micro.
// f32x2 with pairs along the reduction dim (d for S, s for PV):
//   Qs, Ks natural [row][d] (K swizzled), Vst transposed [c][s] (swizzled),
//   Ps natural [m][s].  Accumulators hold (even,odd) partial sums.
// ---------------------------------------------------------------------------
__global__ __launch_bounds__(256) void attn_kernel()
{
    extern __shared__ float sm[];
    float (*Qs)[68]  = (float(*)[68])(sm);
    float (*Ks)[68]  = (float(*)[68])(sm + 64 * 68);
    float (*Vst)[68] = (float(*)[68])(sm + 2 * 64 * 68);
    float (*Ps)[68]  = (float(*)[68])(sm + 3 * 64 * 68);

    const int qb = blockIdx.x;        // 0..31
    const int bh = blockIdx.y;        // 0..63
    const int b = bh >> 4;
    const int h = bh & 15;

    const int tid = threadIdx.x;
    const int tx = tid & 15, ty = tid >> 4;
    const int rm = tid >> 2, rc = (tid & 3) << 4;   // tile loads: 16 floats/thread

    // Load Q tile (natural layout)
    const float* Qg = g_q + ((size_t)bh * Tn + (size_t)qb * 64) * Kd;
#pragma unroll
    for (int q = 0; q < 4; q++)
        *(float4*)&Qs[rm][rc + 4 * q] = *(const float4*)(Qg + rm * 64 + rc + 4 * q);

    float mrow[4], lrow[4];
    u64 o[4][4];
#pragma unroll
    for (int i = 0; i < 4; i++) {
        mrow[i] = -1e30f; lrow[i] = 0.f;
#pragma unroll
        for (int j = 0; j < 4; j++) o[i][j] = 0ull;
    }

    const float SC = 0.125f; // 1/sqrt(64)

    for (int kb = 0; kb <= qb; kb++) {
        const float* Kg = g_k + ((size_t)bh * Tn + (size_t)kb * 64) * Kd;
        const float* Vg = g_v + ((size_t)bh * Tn + (size_t)kb * 64) * Kd;
        __syncthreads();  // protect Ks/Vst/Ps from previous iteration readers
        {
            int swk = ((rm >> 2) & 7) << 2;
#pragma unroll
            for (int q = 0; q < 4; q++)
                *(float4*)&Ks[rm][(rc + 4 * q) ^ swk] =
                    *(const float4*)(Kg + rm * 64 + rc + 4 * q);
#pragma unroll
            for (int q = 0; q < 4; q++) {
                float4 v = *(const float4*)(Vg + rm * 64 + rc + 4 * q);
                float vv[4] = {v.x, v.y, v.z, v.w};
#pragma unroll
                for (int c2 = 0; c2 < 4; c2++) {
                    int c = rc + 4 * q + c2;
                    Vst[c][rm ^ (((c >> 2) & 7) << 2)] = vv[c2];
                }
            }
        }
        __syncthreads();

        // S = Q @ K^T, pairs along d
        u64 s[4][4];
#pragma unroll
        for (int i = 0; i < 4; i++)
#pragma unroll
            for (int j = 0; j < 4; j++) s[i][j] = 0ull;

#pragma unroll 4
        for (int k4 = 0; k4 < 64; k4 += 4) {
            u64 kx[4], ky[4];
#pragma unroll
            for (int j = 0; j < 4; j++) {
                int n = tx + 16 * j;
                ulonglong2 t = *(const ulonglong2*)&Ks[n][k4 ^ (((n >> 2) & 7) << 2)];
                kx[j] = t.x; ky[j] = t.y;
            }
#pragma unroll
            for (int i = 0; i < 4; i++) {
                ulonglong2 qq = *(const ulonglong2*)&Qs[ty * 4 + i][k4];
#pragma unroll
                for (int j = 0; j < 4; j++) {
                    fma2(s[i][j], qq.x, kx[j]);
                    fma2(s[i][j], qq.y, ky[j]);
                }
            }
        }

        // fold pairs, scale, causal mask
        float sc[4][4];
#pragma unroll
        for (int i = 0; i < 4; i++)
#pragma unroll
            for (int j = 0; j < 4; j++) sc[i][j] = sum2(s[i][j]) * SC;

        if (kb == qb) {
#pragma unroll
            for (int i = 0; i < 4; i++) {
                int rr = ty * 4 + i;
#pragma unroll
                for (int j = 0; j < 4; j++) {
                    int cc = tx + 16 * j;
                    if (cc > rr) sc[i][j] = -1e30f;
                }
            }
        }

        // online softmax; row r spans the 16 lanes sharing ty (xor<16 stays in group)
#pragma unroll
        for (int i = 0; i < 4; i++) {
            float rmax = fmaxf(fmaxf(sc[i][0], sc[i][1]), fmaxf(sc[i][2], sc[i][3]));
#pragma unroll
            for (int off = 1; off < 16; off <<= 1)
                rmax = fmaxf(rmax, __shfl_xor_sync(0xffffffffu, rmax, off));
            float mnew = fmaxf(mrow[i], rmax);
            float corr = __expf(mrow[i] - mnew);
            mrow[i] = mnew;
            float rsum = 0.f;
#pragma unroll
            for (int j = 0; j < 4; j++) {
                float p = __expf(sc[i][j] - mnew);
                Ps[ty * 4 + i][tx + 16 * j] = p;
                rsum += p;
            }
#pragma unroll
            for (int off = 1; off < 16; off <<= 1)
                rsum += __shfl_xor_sync(0xffffffffu, rsum, off);
            lrow[i] = lrow[i] * corr + rsum;
            u64 c2 = dup2(corr);
#pragma unroll
            for (int j = 0; j < 4; j++) o[i][j] = mul2(o[i][j], c2);
        }
        __syncthreads();

        // O += P @ V, pairs along s
#pragma unroll 4
        for (int s4 = 0; s4 < 64; s4 += 4) {
            u64 vx[4], vy[4];
#pragma unroll
            for (int j = 0; j < 4; j++) {
                int c = tx + 16 * j;
                ulonglong2 t = *(const ulonglong2*)&Vst[c][s4 ^ (((c >> 2) & 7) << 2)];
                vx[j] = t.x; vy[j] = t.y;
            }
#pragma unroll
            for (int i = 0; i < 4; i++) {
                ulonglong2 pp = *(const ulonglong2*)&Ps[ty * 4 + i][s4];
#pragma unroll
                for (int j = 0; j < 4; j++) {
                    fma2(o[i][j], pp.x, vx[j]);
                    fma2(o[i][j], pp.y, vy[j]);
                }
            }
        }
    }

    // Epilogue: fold pairs, normalize, head-major concat layout [B, T, H*K]
    float* Og = g_ao + ((size_t)b * Tn + (size_t)qb * 64) * HK + (size_t)h * Kd;
#pragma unroll
    for (int i = 0; i < 4; i++) {
        float inv = 1.0f / lrow[i];
#pragma unroll
        for (int j = 0; j < 4; j++)
            Og[(size_t)(ty * 4 + i) * HK + tx + 16 * j] = sum2(o[i][j]) * inv;
    }
}

// ---------------------------------------------------------------------------
// Kernel 3: output projection Y = AO @ Wo^T + bo.  Wo rows are already [n][c]
// (k-major) so no transpose needed; same f32x2 k-pair structure as qkv.
// ---------------------------------------------------------------------------
__global__ __launch_bounds__(256, 2) void proj_kernel(
    const float* __restrict__ Wo,
    const float* __restrict__ bo,
    float* __restrict__ Y)
{
    __shared__ float As[128][36];
    __shared__ float Bs[64][36];

    const int mblk = blockIdx.x;  // 0..63
    const int nblk = blockIdx.y;  // 0..15
    const float* A  = g_ao + (size_t)mblk * 128 * HK;
    const float* Wb = Wo + (size_t)nblk * 64 * HK;

    const int tid = threadIdx.x;
    const int tx = tid & 15, ty = tid >> 4;
    const int a_m = tid >> 1, a_k = (tid & 1) << 4;  // A tile 128x32
    const int b_n = tid >> 2, b_c = (tid & 3) << 3;  // W tile 64x32

    u64 acc[8][4];
#pragma unroll
    for (int i = 0; i < 8; i++)
#pragma unroll
        for (int j = 0; j < 4; j++) acc[i][j] = 0ull;

    for (int kk = 0; kk < HK; kk += 32) {
        float4 a0 = *(const float4*)(A + (size_t)a_m * HK + kk + a_k + 0);
        float4 a1 = *(const float4*)(A + (size_t)a_m * HK + kk + a_k + 4);
        float4 a2 = *(const float4*)(A + (size_t)a_m * HK + kk + a_k + 8);
        float4 a3 = *(const float4*)(A + (size_t)a_m * HK + kk + a_k + 12);
        float4 w0 = *(const float4*)(Wb + (size_t)b_n * HK + kk + b_c + 0);
        float4 w1 = *(const float4*)(Wb + (size_t)b_n * HK + kk + b_c + 4);
        __syncthreads();
        *(float4*)&As[a_m][a_k + 0]  = a0;
        *(float4*)&As[a_m][a_k + 4]  = a1;
        *(float4*)&As[a_m][a_k + 8]  = a2;
        *(float4*)&As[a_m][a_k + 12] = a3;
        {
            int sw = ((b_n >> 2) & 7) << 2;
            *(float4*)&Bs[b_n][(b_c + 0) ^ sw] = w0;
            *(float4*)&Bs[b_n][(b_c + 4) ^ sw] = w1;
        }
        __syncthreads();
#pragma unroll
        for (int k4 = 0; k4 < 32; k4 += 4) {
            u64 bx[4], by[4];
#pragma unroll
            for (int j = 0; j < 4; j++) {
                int n = tx + 16 * j;
                ulonglong2 t = *(const ulonglong2*)&Bs[n][k4 ^ (((n >> 2) & 7) << 2)];
                bx[j] = t.x; by[j] = t.y;
            }
#pragma unroll
            for (int i = 0; i < 8; i++) {
                ulonglong2 aa = *(const ulonglong2*)&As[ty * 8 + i][k4];
#pragma unroll
                for (int j = 0; j < 4; j++) {
                    fma2(acc[i][j], aa.x, bx[j]);
                    fma2(acc[i][j], aa.y, by[j]);
                }
            }
        }
    }

#pragma unroll
    for (int i = 0; i < 8; i++)
#pragma unroll
        for (int j = 0; j < 4; j++) {
            float bias = bo[nblk * 64 + tx + 16 * j];
            Y[(size_t)(mblk * 128 + ty * 8 + i) * HK + nblk * 64 + tx + 16 * j] =
                sum2(acc[i][j]) + bias;
        }
}

// ---------------------------------------------------------------------------
extern "C" void kernel_launch(void* const* d_in, const int* in_sizes, int n_in,
                              void* d_out, int out_size)
{
    (void)in_sizes; (void)n_in; (void)out_size;
    const float* X  = (const float*)d_in[0];
    const float* Wq = (const float*)d_in[1];
    const float* Wk = (const float*)d_in[2];
    const float* Wv = (const float*)d_in[3];
    const float* Wo = (const float*)d_in[4];
    const float* bo = (const float*)d_in[5];
    float* Y = (float*)d_out;

    const int smem = 4 * 64 * 68 * (int)sizeof(float); // 69632
    cudaFuncSetAttribute(attn_kernel, cudaFuncAttributeMaxDynamicSharedMemorySize, smem);

    qkv_kernel<<<dim3(Tn / 128, Bn * Hn, 3), 256>>>(X, Wq, Wk, Wv);
    attn_kernel<<<dim3(Tn / 64, Bn * Hn), 256, smem>>>();
    proj_kernel<<<dim3(Bn * Tn / 128, HK / 64), 256>>>(Wo, bo, Y);
}

// round 3
// speedup vs baseline: 2.4260x; 2.4260x over previous
#include <cuda_runtime.h>
#include <math.h>

// Problem constants
#define Bn 4
#define Tn 2048
#define Dn 1024
#define Hn 16
#define Kd 64
#define HK 1024

// Scratch (device globals; no cudaMalloc allowed)
__device__ float g_q[Bn * Hn * Tn * Kd];
__device__ float g_k[Bn * Hn * Tn * Kd];
__device__ float g_v[Bn * Hn * Tn * Kd];
__device__ float g_ao[Bn * Tn * HK];

// fp32 -> tf32 (round to nearest)
__device__ __forceinline__ unsigned f2tf(float x) {
    unsigned r; asm("cvt.rna.tf32.f32 %0, %1;" : "=r"(r) : "f"(x)); return r;
}

// m16n8k8 TF32 mma, fp32 accumulate.
// A row-major 16x8: a0=(g,tig) a1=(g+8,tig) a2=(g,tig+4) a3=(g+8,tig+4)
// B col 8x8:        b0=(k=tig,n=g) b1=(k=tig+4,n=g)
// C 16x8:           c0=(g,2tig) c1=(g,2tig+1) c2=(g+8,2tig) c3=(g+8,2tig+1)
__device__ __forceinline__ void mma8(float* c, const unsigned* a, unsigned b0, unsigned b1) {
    asm("mma.sync.aligned.m16n8k8.row.col.f32.tf32.tf32.f32 "
        "{%0,%1,%2,%3}, {%4,%5,%6,%7}, {%8,%9}, {%0,%1,%2,%3};"
        : "+f"(c[0]), "+f"(c[1]), "+f"(c[2]), "+f"(c[3])
        : "r"(a[0]), "r"(a[1]), "r"(a[2]), "r"(a[3]), "r"(b0), "r"(b1));
}

// ---------------------------------------------------------------------------
// Kernel 1: fused QKV GEMM.  C[8192 x 3072] = X[8192 x 1024] @ Wall,
// where Wall columns n = which*1024 + h*64 + k gather W{q,k,v}[h][:,k].
// Block tile 128m x 128n, k-chunk 32. 8 warps (4m x 2n), warp 32m x 64n.
// ---------------------------------------------------------------------------
__global__ __launch_bounds__(256, 2) void qkv_mma(
    const float* __restrict__ X,
    const float* __restrict__ Wq,
    const float* __restrict__ Wk,
    const float* __restrict__ Wv)
{
    __shared__ unsigned As[128][40];   // [m][k], stride%32==8
    __shared__ unsigned Bs[32][136];   // [k][n], stride%32==8

    const int mblk = blockIdx.x;       // 0..63
    const int nblk = blockIdx.y;       // 0..23
    const int which = nblk >> 3;       // 128-col tile lies inside one 1024 group
    const float* W = (which == 0) ? Wq : (which == 1) ? Wk : Wv;
    float* outW = (which == 0) ? g_q : (which == 1) ? g_k : g_v;

    const float* A = X + (size_t)mblk * 128 * Dn;

    const int tid = threadIdx.x;
    const int w = tid >> 5, lane = tid & 31;
    const int g = lane >> 2, tig = lane & 3;
    const int wm = w >> 1, wn = w & 1;

    float acc[2][8][4];
#pragma unroll
    for (int mi = 0; mi < 2; mi++)
#pragma unroll
        for (int ni = 0; ni < 8; ni++)
#pragma unroll
            for (int q = 0; q < 4; q++) acc[mi][ni][q] = 0.f;

    for (int kk = 0; kk < Dn; kk += 32) {
        float4 av[4], wv[4];
#pragma unroll
        for (int r = 0; r < 4; r++) {
            int idx = tid + 256 * r;
            int row = idx >> 3, c4 = (idx & 7) << 2;
            av[r] = *(const float4*)(A + (size_t)row * Dn + kk + c4);
            int brow = idx >> 5, bc4 = (idx & 31) << 2;
            int ng = nblk * 128 + bc4;
            int hh = (ng >> 6) & 15, kcol = ng & 63;
            wv[r] = *(const float4*)(W + (size_t)hh * Dn * Kd + (size_t)(kk + brow) * Kd + kcol);
        }
        __syncthreads();
#pragma unroll
        for (int r = 0; r < 4; r++) {
            int idx = tid + 256 * r;
            int row = idx >> 3, c4 = (idx & 7) << 2;
            As[row][c4 + 0] = f2tf(av[r].x);
            As[row][c4 + 1] = f2tf(av[r].y);
            As[row][c4 + 2] = f2tf(av[r].z);
            As[row][c4 + 3] = f2tf(av[r].w);
            int brow = idx >> 5, bc4 = (idx & 31) << 2;
            Bs[brow][bc4 + 0] = f2tf(wv[r].x);
            Bs[brow][bc4 + 1] = f2tf(wv[r].y);
            Bs[brow][bc4 + 2] = f2tf(wv[r].z);
            Bs[brow][bc4 + 3] = f2tf(wv[r].w);
        }
        __syncthreads();

#pragma unroll
        for (int ks = 0; ks < 4; ks++) {
            const int k0 = ks * 8;
            unsigned af[2][4];
#pragma unroll
            for (int mi = 0; mi < 2; mi++) {
                int m0 = wm * 32 + mi * 16;
                af[mi][0] = As[m0 + g][k0 + tig];
                af[mi][1] = As[m0 + g + 8][k0 + tig];
                af[mi][2] = As[m0 + g][k0 + tig + 4];
                af[mi][3] = As[m0 + g + 8][k0 + tig + 4];
            }
#pragma unroll
            for (int ni = 0; ni < 8; ni++) {
                int n0 = wn * 64 + ni * 8;
                unsigned b0 = Bs[k0 + tig][n0 + g];
                unsigned b1 = Bs[k0 + tig + 4][n0 + g];
                mma8(acc[0][ni], af[0], b0, b1);
                mma8(acc[1][ni], af[1], b0, b1);
            }
        }
    }

    // Epilogue: scatter into g_q/g_k/g_v [bh][t][k]
#pragma unroll
    for (int mi = 0; mi < 2; mi++) {
        int m = mblk * 128 + wm * 32 + mi * 16 + g;
        int b = m >> 11, t = m & 2047;
#pragma unroll
        for (int ni = 0; ni < 8; ni++) {
            int ng = nblk * 128 + wn * 64 + ni * 8 + 2 * tig;
            int hh = (ng >> 6) & 15, kcol = ng & 63;
            float* p = outW + ((size_t)(b * 16 + hh) * Tn + t) * Kd + kcol;
            *(float2*)p = make_float2(acc[mi][ni][0], acc[mi][ni][1]);
            *(float2*)(p + 8 * Kd) = make_float2(acc[mi][ni][2], acc[mi][ni][3]);
        }
    }
}

// ---------------------------------------------------------------------------
// Kernel 2: causal flash attention with TF32 tensor cores.
// 256 threads (8 warps), 128-query tile, 64-key tiles. Warp w owns 16 q-rows.
// Q fragments register-resident; P staged through warp-private smem rows.
// ---------------------------------------------------------------------------
__global__ __launch_bounds__(256, 2) void attn_kernel()
{
    extern __shared__ unsigned smu[];
    unsigned (*QP)[72] = (unsigned(*)[72])smu;                    // 128 rows: Q then P
    unsigned (*Ks)[72] = (unsigned(*)[72])(smu + 128 * 72);       // 64 rows
    unsigned (*Vs)[72] = (unsigned(*)[72])(smu + (128 + 64) * 72);// 64 rows

    const int qb = (int)gridDim.x - 1 - (int)blockIdx.x;  // reversed: big tiles first
    const int bh = blockIdx.y;
    const int b = bh >> 4, h = bh & 15;

    const int tid = threadIdx.x;
    const int w = tid >> 5, lane = tid & 31;
    const int g = lane >> 2, tig = lane & 3;
    const int r0 = w * 16 + g;          // local q-row of c0/c1
    const float SC = 0.125f;            // 1/sqrt(64), exact in tf32

    // Load+scale+convert Q tile (128 x 64)
    const float* Qg = g_q + ((size_t)bh * Tn + (size_t)qb * 128) * Kd;
#pragma unroll
    for (int r = 0; r < 8; r++) {
        int idx = tid + 256 * r;
        int row = idx >> 4, c4 = (idx & 15) << 2;
        float4 v = *(const float4*)(Qg + (size_t)row * Kd + c4);
        QP[row][c4 + 0] = f2tf(v.x * SC);
        QP[row][c4 + 1] = f2tf(v.y * SC);
        QP[row][c4 + 2] = f2tf(v.z * SC);
        QP[row][c4 + 3] = f2tf(v.w * SC);
    }
    __syncthreads();

    unsigned qf[8][4];
#pragma unroll
    for (int ks = 0; ks < 8; ks++) {
        int k0 = ks * 8;
        qf[ks][0] = QP[r0][k0 + tig];
        qf[ks][1] = QP[r0 + 8][k0 + tig];
        qf[ks][2] = QP[r0][k0 + tig + 4];
        qf[ks][3] = QP[r0 + 8][k0 + tig + 4];
    }
    // After extraction, QP rows [w*16, w*16+16) are warp-private P storage.

    float m0 = -1e30f, m1 = -1e30f, l0 = 0.f, l1 = 0.f;
    float o[8][4];
#pragma unroll
    for (int ni = 0; ni < 8; ni++)
#pragma unroll
        for (int q = 0; q < 4; q++) o[ni][q] = 0.f;

    const int kbmax = 2 * qb + 1;
    for (int kb = 0; kb <= kbmax; kb++) {
        __syncthreads();  // all warps done with previous Ks/Vs
        const float* Kg = g_k + ((size_t)bh * Tn + (size_t)kb * 64) * Kd;
        const float* Vg = g_v + ((size_t)bh * Tn + (size_t)kb * 64) * Kd;
#pragma unroll
        for (int r = 0; r < 4; r++) {
            int idx = tid + 256 * r;
            int row = idx >> 4, c4 = (idx & 15) << 2;
            float4 kv = *(const float4*)(Kg + (size_t)row * Kd + c4);
            float4 vv = *(const float4*)(Vg + (size_t)row * Kd + c4);
            Ks[row][c4 + 0] = f2tf(kv.x); Ks[row][c4 + 1] = f2tf(kv.y);
            Ks[row][c4 + 2] = f2tf(kv.z); Ks[row][c4 + 3] = f2tf(kv.w);
            Vs[row][c4 + 0] = f2tf(vv.x); Vs[row][c4 + 1] = f2tf(vv.y);
            Vs[row][c4 + 2] = f2tf(vv.z); Vs[row][c4 + 3] = f2tf(vv.w);
        }
        __syncthreads();

        // S = Q @ K^T
        float s[8][4];
#pragma unroll
        for (int ni = 0; ni < 8; ni++)
#pragma unroll
            for (int q = 0; q < 4; q++) s[ni][q] = 0.f;
#pragma unroll
        for (int ks = 0; ks < 8; ks++) {
            int k0 = ks * 8;
#pragma unroll
            for (int ni = 0; ni < 8; ni++) {
                unsigned b0 = Ks[ni * 8 + g][k0 + tig];
                unsigned b1 = Ks[ni * 8 + g][k0 + tig + 4];
                mma8(s[ni], qf[ks], b0, b1);
            }
        }

        // Causal mask (only tiles touching/above the diagonal)
        if (kb >= 2 * qb) {
            int grow0 = qb * 128 + r0;
#pragma unroll
            for (int ni = 0; ni < 8; ni++) {
                int col = kb * 64 + ni * 8 + 2 * tig;
                if (col > grow0)         s[ni][0] = -1e30f;
                if (col + 1 > grow0)     s[ni][1] = -1e30f;
                if (col > grow0 + 8)     s[ni][2] = -1e30f;
                if (col + 1 > grow0 + 8) s[ni][3] = -1e30f;
            }
        }

        // Online softmax (rows r0 and r0+8; 4-lane groups share a row)
        float x0 = -1e30f, x1 = -1e30f;
#pragma unroll
        for (int ni = 0; ni < 8; ni++) {
            x0 = fmaxf(x0, fmaxf(s[ni][0], s[ni][1]));
            x1 = fmaxf(x1, fmaxf(s[ni][2], s[ni][3]));
        }
#pragma unroll
        for (int off = 1; off < 4; off <<= 1) {
            x0 = fmaxf(x0, __shfl_xor_sync(0xffffffffu, x0, off));
            x1 = fmaxf(x1, __shfl_xor_sync(0xffffffffu, x1, off));
        }
        float mn0 = fmaxf(m0, x0), mn1 = fmaxf(m1, x1);
        float corr0 = __expf(m0 - mn0), corr1 = __expf(m1 - mn1);
        m0 = mn0; m1 = mn1;

        float rs0 = 0.f, rs1 = 0.f;
#pragma unroll
        for (int ni = 0; ni < 8; ni++) {
            float e0 = __expf(s[ni][0] - m0);
            float e1 = __expf(s[ni][1] - m0);
            float e2 = __expf(s[ni][2] - m1);
            float e3 = __expf(s[ni][3] - m1);
            unsigned t0 = f2tf(e0), t1 = f2tf(e1), t2 = f2tf(e2), t3 = f2tf(e3);
            rs0 += __uint_as_float(t0) + __uint_as_float(t1);
            rs1 += __uint_as_float(t2) + __uint_as_float(t3);
            int col = ni * 8 + 2 * tig;
            QP[r0][col] = t0;     QP[r0][col + 1] = t1;
            QP[r0 + 8][col] = t2; QP[r0 + 8][col + 1] = t3;
        }
#pragma unroll
        for (int off = 1; off < 4; off <<= 1) {
            rs0 += __shfl_xor_sync(0xffffffffu, rs0, off);
            rs1 += __shfl_xor_sync(0xffffffffu, rs1, off);
        }
        l0 = l0 * corr0 + rs0;
        l1 = l1 * corr1 + rs1;
#pragma unroll
        for (int ni = 0; ni < 8; ni++) {
            o[ni][0] *= corr0; o[ni][1] *= corr0;
            o[ni][2] *= corr1; o[ni][3] *= corr1;
        }
        __syncwarp();

        // O += P @ V
#pragma unroll
        for (int ss = 0; ss < 8; ss++) {
            int s0 = ss * 8;
            unsigned pa[4];
            pa[0] = QP[r0][s0 + tig];
            pa[1] = QP[r0 + 8][s0 + tig];
            pa[2] = QP[r0][s0 + tig + 4];
            pa[3] = QP[r0 + 8][s0 + tig + 4];
#pragma unroll
            for (int ni = 0; ni < 8; ni++) {
                unsigned b0 = Vs[s0 + tig][ni * 8 + g];
                unsigned b1 = Vs[s0 + tig + 4][ni * 8 + g];
                mma8(o[ni], pa, b0, b1);
            }
        }
    }

    // Epilogue: normalize, write [B, T, H*K] head-concat layout
    float inv0 = 1.0f / l0, inv1 = 1.0f / l1;
    float* Og = g_ao + ((size_t)b * Tn + (size_t)qb * 128 + w * 16) * HK + (size_t)h * Kd;
#pragma unroll
    for (int ni = 0; ni < 8; ni++) {
        int col = ni * 8 + 2 * tig;
        *(float2*)(Og + (size_t)g * HK + col) =
            make_float2(o[ni][0] * inv0, o[ni][1] * inv0);
        *(float2*)(Og + (size_t)(g + 8) * HK + col) =
            make_float2(o[ni][2] * inv1, o[ni][3] * inv1);
    }
}

// ---------------------------------------------------------------------------
// Kernel 3: output projection Y = AO @ Wo^T + bo.  M=8192, N=1024, K=1024.
// Same skeleton: 128x128 tile, B fragments straight from Wo rows (k-major).
// ---------------------------------------------------------------------------
__global__ __launch_bounds__(256, 2) void proj_mma(
    const float* __restrict__ Wo,
    const float* __restrict__ bo,
    float* __restrict__ Y)
{
    __shared__ unsigned As[128][40];   // [m][k]
    __shared__ unsigned Ws[128][40];   // [n][k]

    const int mblk = blockIdx.x;  // 0..63
    const int nblk = blockIdx.y;  // 0..7
    const float* A = g_ao + (size_t)mblk * 128 * HK;

    const int tid = threadIdx.x;
    const int w = tid >> 5, lane = tid & 31;
    const int g = lane >> 2, tig = lane & 3;
    const int wm = w >> 1, wn = w & 1;

    float acc[2][8][4];
#pragma unroll
    for (int mi = 0; mi < 2; mi++)
#pragma unroll
        for (int ni = 0; ni < 8; ni++)
#pragma unroll
            for (int q = 0; q < 4; q++) acc[mi][ni][q] = 0.f;

    for (int kk = 0; kk < HK; kk += 32) {
        float4 av[4], wv[4];
#pragma unroll
        for (int r = 0; r < 4; r++) {
            int idx = tid + 256 * r;
            int row = idx >> 3, c4 = (idx & 7) << 2;
            av[r] = *(const float4*)(A + (size_t)row * HK + kk + c4);
            wv[r] = *(const float4*)(Wo + (size_t)(nblk * 128 + row) * HK + kk + c4);
        }
        __syncthreads();
#pragma unroll
        for (int r = 0; r < 4; r++) {
            int idx = tid + 256 * r;
            int row = idx >> 3, c4 = (idx & 7) << 2;
            As[row][c4 + 0] = f2tf(av[r].x);
            As[row][c4 + 1] = f2tf(av[r].y);
            As[row][c4 + 2] = f2tf(av[r].z);
            As[row][c4 + 3] = f2tf(av[r].w);
            Ws[row][c4 + 0] = f2tf(wv[r].x);
            Ws[row][c4 + 1] = f2tf(wv[r].y);
            Ws[row][c4 + 2] = f2tf(wv[r].z);
            Ws[row][c4 + 3] = f2tf(wv[r].w);
        }
        __syncthreads();

#pragma unroll
        for (int ks = 0; ks < 4; ks++) {
            const int k0 = ks * 8;
            unsigned af[2][4];
#pragma unroll
            for (int mi = 0; mi < 2; mi++) {
                int m0 = wm * 32 + mi * 16;
                af[mi][0] = As[m0 + g][k0 + tig];
                af[mi][1] = As[m0 + g + 8][k0 + tig];
                af[mi][2] = As[m0 + g][k0 + tig + 4];
                af[mi][3] = As[m0 + g + 8][k0 + tig + 4];
            }
#pragma unroll
            for (int ni = 0; ni < 8; ni++) {
                int n0 = wn * 64 + ni * 8;
                unsigned b0 = Ws[n0 + g][k0 + tig];
                unsigned b1 = Ws[n0 + g][k0 + tig + 4];
                mma8(acc[0][ni], af[0], b0, b1);
                mma8(acc[1][ni], af[1], b0, b1);
            }
        }
    }

#pragma unroll
    for (int mi = 0; mi < 2; mi++) {
        int m = mblk * 128 + wm * 32 + mi * 16 + g;
#pragma unroll
        for (int ni = 0; ni < 8; ni++) {
            int n = nblk * 128 + wn * 64 + ni * 8 + 2 * tig;
            float2 bb = *(const float2*)(bo + n);
            *(float2*)(Y + (size_t)m * HK + n) =
                make_float2(acc[mi][ni][0] + bb.x, acc[mi][ni][1] + bb.y);
            *(float2*)(Y + (size_t)(m + 8) * HK + n) =
                make_float2(acc[mi][ni][2] + bb.x, acc[mi][ni][3] + bb.y);
        }
    }
}

// ---------------------------------------------------------------------------
extern "C" void kernel_launch(void* const* d_in, const int* in_sizes, int n_in,
                              void* d_out, int out_size)
{
    (void)in_sizes; (void)n_in; (void)out_size;
    const float* X  = (const float*)d_in[0];
    const float* Wq = (const float*)d_in[1];
    const float* Wk = (const float*)d_in[2];
    const float* Wv = (const float*)d_in[3];
    const float* Wo = (const float*)d_in[4];
    const float* bo = (const float*)d_in[5];
    float* Y = (float*)d_out;

    const int attn_smem = (128 + 64 + 64) * 72 * (int)sizeof(unsigned); // 73728
    cudaFuncSetAttribute(attn_kernel, cudaFuncAttributeMaxDynamicSharedMemorySize, attn_smem);

    qkv_mma<<<dim3(64, 24), 256>>>(X, Wq, Wk, Wv);
    attn_kernel<<<dim3(Tn / 128, Bn * Hn), 256, attn_smem>>>();
    proj_mma<<<dim3(64, 8), 256>>>(Wo, bo, Y);
}

// round 4
// speedup vs baseline: 4.9139x; 2.0255x over previous
#include <cuda_runtime.h>

// Problem constants
#define Bn 4
#define Tn 2048
#define Dn 1024
#define Hn 16
#define Kd 64
#define HK 1024

// ---- tf32 scratch (bit patterns stored as unsigned) ----
__device__ unsigned g_xt[Bn * Tn * Dn];          // X tf32 [8192][1024]
__device__ unsigned g_wall[3072 * 1024];         // gathered W^T tf32 [n][d]
__device__ unsigned g_wot[1024 * 1024];          // Wo tf32 [n][k]
__device__ unsigned g_q[Bn * Hn * Tn * Kd];      // tf32, pre-scaled [bh][t][d]
__device__ unsigned g_k[Bn * Hn * Tn * Kd];      // tf32 [bh][t][d]
__device__ unsigned g_vt[Bn * Hn * Kd * Tn];     // tf32 [bh][d][t]
__device__ unsigned g_ao[Bn * Tn * HK];          // tf32 [b*t][h*64+c]

__device__ __forceinline__ unsigned f2tf(float x) {
    unsigned r; asm("cvt.rna.tf32.f32 %0, %1;" : "=r"(r) : "f"(x)); return r;
}
__device__ __forceinline__ void mma8(float* c, const unsigned* a, unsigned b0, unsigned b1) {
    asm("mma.sync.aligned.m16n8k8.row.col.f32.tf32.tf32.f32 "
        "{%0,%1,%2,%3}, {%4,%5,%6,%7}, {%8,%9}, {%0,%1,%2,%3};"
        : "+f"(c[0]), "+f"(c[1]), "+f"(c[2]), "+f"(c[3])
        : "r"(a[0]), "r"(a[1]), "r"(a[2]), "r"(a[3]), "r"(b0), "r"(b1));
}
__device__ __forceinline__ void ldsm4(unsigned r[4], unsigned addr) {
    asm volatile("ldmatrix.sync.aligned.m8n8.x4.shared.b16 {%0,%1,%2,%3}, [%4];"
                 : "=r"(r[0]), "=r"(r[1]), "=r"(r[2]), "=r"(r[3]) : "r"(addr));
}
__device__ __forceinline__ void cpa16(unsigned d, const void* s) {
    asm volatile("cp.async.ca.shared.global [%0], [%1], 16;" :: "r"(d), "l"(s));
}
#define CP_COMMIT asm volatile("cp.async.commit_group;")
#define CP_WAIT0  asm volatile("cp.async.wait_group 0;")
__device__ __forceinline__ unsigned cvta_s(const void* p) {
    return (unsigned)__cvta_generic_to_shared(p);
}

// ---------------------------------------------------------------------------
// Prepass A: elementwise fp32->tf32 for X and Wo
// ---------------------------------------------------------------------------
__global__ __launch_bounds__(256) void conv_kernel(const float4* __restrict__ X,
                                                   const float4* __restrict__ Wo)
{
    int idx = blockIdx.x * 256 + threadIdx.x;   // grid 8192 -> idx < 2097152
    float4 v = X[idx];
    uint4 o;
    o.x = f2tf(v.x); o.y = f2tf(v.y); o.z = f2tf(v.z); o.w = f2tf(v.w);
    *(uint4*)&g_xt[idx * 4] = o;
    if (idx < 262144) {
        float4 w = Wo[idx];
        uint4 ow;
        ow.x = f2tf(w.x); ow.y = f2tf(w.y); ow.z = f2tf(w.z); ow.w = f2tf(w.w);
        *(uint4*)&g_wot[idx * 4] = ow;
    }
}

// ---------------------------------------------------------------------------
// Prepass B: gather+transpose W{q,k,v}[h] (D x 64, k-major) -> g_wall[n][d]
// ---------------------------------------------------------------------------
__global__ __launch_bounds__(256) void gather_w(const float* __restrict__ Wq,
                                                const float* __restrict__ Wk,
                                                const float* __restrict__ Wv)
{
    __shared__ unsigned t[32][65];
    const int d0 = blockIdx.x * 32;
    const int wh = blockIdx.y;            // 0..47
    const int which = wh >> 4, h = wh & 15;
    const float* W = ((which == 0) ? Wq : (which == 1) ? Wk : Wv) + (size_t)h * Dn * Kd;
    const int tid = threadIdx.x;
#pragma unroll
    for (int i = 0; i < 8; i++) {
        int idx = tid + 256 * i;
        int dr = idx >> 6, c = idx & 63;
        t[dr][c] = f2tf(W[(size_t)(d0 + dr) * 64 + c]);
    }
    __syncthreads();
#pragma unroll
    for (int i = 0; i < 8; i++) {
        int idx = tid + 256 * i;
        int row = idx >> 5, dd = idx & 31;
        g_wall[(size_t)((which << 10) + (h << 6) + row) * 1024 + d0 + dd] = t[dd][row];
    }
}

// ---------------------------------------------------------------------------
// GEMM mainloop (shared shape): C[128x128] tile, K in 32-chunks, cp.async
// double buffered, ldmatrix fragments, XOR-swizzled smem (32-word rows).
// 8 warps: wm=w>>1 (4), wn=w&1 (2); warp tile 32m x 64n.
// ---------------------------------------------------------------------------
#define GEMM_MAIN(Aptr, Bptr, KTOT)                                              \
    const int tid = threadIdx.x;                                                 \
    const int w = tid >> 5, lane = tid & 31;                                     \
    const int g = lane >> 2, tig = lane & 3;                                     \
    const int wm = w >> 1, wn = w & 1;                                           \
    const int rl = lane & 7, sub = lane >> 3;                                    \
    const int shA = sub >> 1, shB = sub & 1;                                     \
    extern __shared__ unsigned sm[];                                             \
    const unsigned sA = cvta_s(sm);                                              \
    const unsigned sB = sA + 2 * 4096 * 4;                                       \
    /* fill mapping: idx = tid+256i -> row=(tid>>3)+32i, chunk c=tid&7 */        \
    const int r0f = tid >> 3, cf = tid & 7;                                      \
    const unsigned dA0 = sA + ((r0f * 32 + ((cf ^ (r0f & 7)) << 2)) << 2);       \
    const unsigned dB0 = sB + ((r0f * 32 + ((cf ^ (r0f & 7)) << 2)) << 2);       \
    /* ldsm lane constants */                                                    \
    int rowA0 = wm * 32 + ((sub & 1) << 3) + rl;                                 \
    int wA0 = rowA0 * 32, xA0 = rowA0 & 7;                                       \
    int wA1 = (rowA0 + 16) * 32, xA1 = (rowA0 + 16) & 7;                         \
    int rowB0 = wn * 64 + ((sub >> 1) << 3) + rl;                                \
    int wB[4], xB[4];                                                            \
    _Pragma("unroll") for (int nj = 0; nj < 4; nj++) {                           \
        int rb = rowB0 + nj * 16; wB[nj] = rb * 32; xB[nj] = rb & 7; }           \
    float acc[2][8][4];                                                          \
    _Pragma("unroll") for (int mi = 0; mi < 2; mi++)                             \
    _Pragma("unroll") for (int ni = 0; ni < 8; ni++)                             \
    _Pragma("unroll") for (int q = 0; q < 4; q++) acc[mi][ni][q] = 0.f;          \
    /* prefetch stage 0 */                                                       \
    _Pragma("unroll") for (int i = 0; i < 4; i++) {                              \
        cpa16(dA0 + i * 4096, Aptr + (size_t)(r0f + 32 * i) * 1024 + cf * 4);    \
        cpa16(dB0 + i * 4096, Bptr + (size_t)(r0f + 32 * i) * 1024 + cf * 4); }  \
    CP_COMMIT;                                                                   \
    const int NIT = (KTOT) / 32;                                                 \
    for (int it = 0; it < NIT; it++) {                                           \
        CP_WAIT0; __syncthreads();                                               \
        int buf = it & 1;                                                        \
        if (it + 1 < NIT) {                                                      \
            int kk = (it + 1) * 32;                                              \
            unsigned off = (buf ^ 1) * 16384;                                    \
            _Pragma("unroll") for (int i = 0; i < 4; i++) {                      \
                cpa16(dA0 + off + i * 4096,                                      \
                      Aptr + (size_t)(r0f + 32 * i) * 1024 + kk + cf * 4);       \
                cpa16(dB0 + off + i * 4096,                                      \
                      Bptr + (size_t)(r0f + 32 * i) * 1024 + kk + cf * 4); }     \
            CP_COMMIT;                                                           \
        }                                                                        \
        unsigned stoff = buf * 16384;                                            \
        _Pragma("unroll") for (int ks = 0; ks < 4; ks++) {                       \
            unsigned a0[4], a1[4], bq[4][4];                                     \
            ldsm4(a0, sA + stoff + ((wA0 + (((2 * ks + shA) ^ xA0) << 2)) << 2));\
            ldsm4(a1, sA + stoff + ((wA1 + (((2 * ks + shA) ^ xA1) << 2)) << 2));\
            _Pragma("unroll") for (int nj = 0; nj < 4; nj++)                     \
                ldsm4(bq[nj], sB + stoff +                                       \
                      ((wB[nj] + (((2 * ks + shB) ^ xB[nj]) << 2)) << 2));       \
            _Pragma("unroll") for (int ni = 0; ni < 8; ni++) {                   \
                unsigned b0 = bq[ni >> 1][(ni & 1) * 2];                         \
                unsigned b1 = bq[ni >> 1][(ni & 1) * 2 + 1];                     \
                mma8(acc[0][ni], a0, b0, b1);                                    \
                mma8(acc[1][ni], a1, b0, b1);                                    \
            }                                                                    \
        }                                                                        \
    }

// ---------------------------------------------------------------------------
// Kernel 1: fused QKV GEMM, epilogue scatters tf32 into g_q/g_k/g_vt.
// ---------------------------------------------------------------------------
__global__ __launch_bounds__(256, 2) void qkv_mma()
{
    const int mblk = blockIdx.x;          // 0..63
    const int nblk = blockIdx.y;          // 0..23
    const unsigned* Ag = g_xt + (size_t)mblk * 128 * Dn;
    const unsigned* Bg = g_wall + (size_t)nblk * 128 * 1024;

    GEMM_MAIN(Ag, Bg, 1024)

    const int which = nblk >> 3;
#pragma unroll
    for (int mi = 0; mi < 2; mi++) {
        int m = mblk * 128 + wm * 32 + mi * 16 + g;
        int b = m >> 11, t = m & 2047;
#pragma unroll
        for (int ni = 0; ni < 8; ni++) {
            int nl = nblk * 128 + wn * 64 + ni * 8 + 2 * tig;
            int hh = (nl >> 6) & 15, kcol = nl & 63;
            float c0 = acc[mi][ni][0], c1 = acc[mi][ni][1];
            float c2 = acc[mi][ni][2], c3 = acc[mi][ni][3];
            if (which == 0) {
                unsigned* p = g_q + ((size_t)(b * 16 + hh) * Tn + t) * 64 + kcol;
                *(uint2*)p = make_uint2(f2tf(c0 * 0.125f), f2tf(c1 * 0.125f));
                *(uint2*)(p + 8 * 64) = make_uint2(f2tf(c2 * 0.125f), f2tf(c3 * 0.125f));
            } else if (which == 1) {
                unsigned* p = g_k + ((size_t)(b * 16 + hh) * Tn + t) * 64 + kcol;
                *(uint2*)p = make_uint2(f2tf(c0), f2tf(c1));
                *(uint2*)(p + 8 * 64) = make_uint2(f2tf(c2), f2tf(c3));
            } else {
                unsigned* p = g_vt + ((size_t)(b * 16 + hh) * 64 + kcol) * Tn + t;
                p[0] = f2tf(c0); p[Tn] = f2tf(c1);
                p[8] = f2tf(c2); p[Tn + 8] = f2tf(c3);
            }
        }
    }
}

// ---------------------------------------------------------------------------
// Kernel 3: output projection, epilogue adds bias, writes fp32 Y.
// ---------------------------------------------------------------------------
__global__ __launch_bounds__(256, 2) void proj_mma(const float* __restrict__ bo,
                                                   float* __restrict__ Y)
{
    const int mblk = blockIdx.x;  // 0..63
    const int nblk = blockIdx.y;  // 0..7
    const unsigned* Ag = g_ao + (size_t)mblk * 128 * HK;
    const unsigned* Bg = g_wot + (size_t)nblk * 128 * 1024;

    GEMM_MAIN(Ag, Bg, 1024)

#pragma unroll
    for (int mi = 0; mi < 2; mi++) {
        int m = mblk * 128 + wm * 32 + mi * 16 + g;
#pragma unroll
        for (int ni = 0; ni < 8; ni++) {
            int n = nblk * 128 + wn * 64 + ni * 8 + 2 * tig;
            float2 bb = *(const float2*)(bo + n);
            *(float2*)(Y + (size_t)m * HK + n) =
                make_float2(acc[0 + mi][ni][0] + bb.x, acc[mi][ni][1] + bb.y);
            *(float2*)(Y + (size_t)(m + 8) * HK + n) =
                make_float2(acc[mi][ni][2] + bb.x, acc[mi][ni][3] + bb.y);
        }
    }
}

// ---------------------------------------------------------------------------
// Kernel 2: causal flash attention, TF32 mma + ldmatrix + cp.async dbl-buffer.
// 128q tile, 64k tiles.  Q [t][d], K [s][d], V^T [d][t] all tf32 in gmem.
// smem: QP (Q then P) 128x64, K 2x64x64, V 2x64x64 (64-word swizzled rows).
// ---------------------------------------------------------------------------
__global__ __launch_bounds__(256, 2) void attn_kernel()
{
    extern __shared__ unsigned sm[];
    const unsigned sQ = cvta_s(sm);
    const unsigned sK = sQ + 8192 * 4;
    const unsigned sV = sK + 2 * 4096 * 4;

    const int qb = (int)gridDim.x - 1 - (int)blockIdx.x;
    const int bh = blockIdx.y;
    const int b = bh >> 4, h = bh & 15;

    const int tid = threadIdx.x;
    const int w = tid >> 5, lane = tid & 31;
    const int g = lane >> 2, tig = lane & 3;
    const int rl = lane & 7, sub = lane >> 3;

    const unsigned* Qg = g_q + ((size_t)bh * Tn + (size_t)qb * 128) * 64;
    const unsigned* Kg = g_k + (size_t)bh * Tn * 64;
    const unsigned* Vt = g_vt + (size_t)bh * 64 * Tn;

    // fill mapping (64-word rows, 16 chunks): row=(tid>>4)+16i, c=tid&15
    const int frow = tid >> 4, fc = tid & 15;
    const unsigned foff = ((frow * 64 + ((fc >> 3) << 5) +
                            (((fc & 7) ^ (frow & 7)) << 2)) << 2);

    // prefetch Q + K0 + V0
#pragma unroll
    for (int i = 0; i < 8; i++)
        cpa16(sQ + foff + i * 4096, Qg + (size_t)(frow + 16 * i) * 64 + fc * 4);
#pragma unroll
    for (int i = 0; i < 4; i++) {
        cpa16(sK + foff + i * 4096, Kg + (size_t)(frow + 16 * i) * 64 + fc * 4);
        cpa16(sV + foff + i * 4096, Vt + (size_t)(frow + 16 * i) * Tn + fc * 4);
    }
    CP_COMMIT;
    CP_WAIT0;
    __syncthreads();

    // extract Q fragments (warp-private rows w*16..w*16+15)
    const int rowQ = w * 16 + ((sub & 1) << 3) + rl;
    const int wq = rowQ * 64, xq = rowQ & 7, shq = sub >> 1;
    unsigned qf[8][4];
#pragma unroll
    for (int ks = 0; ks < 8; ks++) {
        unsigned addr = sQ + ((wq + ((ks & 4) << 3) +
                               ((((2 * ks) & 7) + shq ^ xq) << 2)) << 2);
        ldsm4(qf[ks], addr);
    }

    // B-fragment lane constants (shared by K rows s and V rows d)
    int rowB0 = ((sub >> 1) << 3) + rl;
    int wKB[4], xKB[4];
#pragma unroll
    for (int nj = 0; nj < 4; nj++) {
        int rb = rowB0 + nj * 16; wKB[nj] = rb * 64; xKB[nj] = rb & 7;
    }
    const int shb = sub & 1;

    float m0 = -1e30f, m1 = -1e30f, l0 = 0.f, l1 = 0.f;
    float o[8][4];
#pragma unroll
    for (int ni = 0; ni < 8; ni++)
#pragma unroll
        for (int q = 0; q < 4; q++) o[ni][q] = 0.f;

    const int r0 = w * 16 + g;
    const int kbmax = 2 * qb + 1;

    for (int kb = 0; kb <= kbmax; kb++) {
        const int buf = kb & 1;
        if (kb) { CP_WAIT0; __syncthreads(); }
        if (kb < kbmax) {
            unsigned off = (buf ^ 1) * 16384;
            int s0g = (kb + 1) * 64;
#pragma unroll
            for (int i = 0; i < 4; i++) {
                cpa16(sK + off + foff + i * 4096,
                      Kg + (size_t)(s0g + frow + 16 * i) * 64 + fc * 4);
                cpa16(sV + off + foff + i * 4096,
                      Vt + (size_t)(frow + 16 * i) * Tn + s0g + fc * 4);
            }
            CP_COMMIT;
        }
        const unsigned stK = sK + buf * 16384;
        const unsigned stV = sV + buf * 16384;

        // S = Q @ K^T
        float s[8][4];
#pragma unroll
        for (int ni = 0; ni < 8; ni++)
#pragma unroll
            for (int q = 0; q < 4; q++) s[ni][q] = 0.f;
#pragma unroll
        for (int ks = 0; ks < 8; ks++) {
            unsigned bq[4][4];
#pragma unroll
            for (int nj = 0; nj < 4; nj++)
                ldsm4(bq[nj], stK + ((wKB[nj] + ((ks & 4) << 3) +
                      ((((2 * ks) & 7) + shb ^ xKB[nj]) << 2)) << 2));
#pragma unroll
            for (int ni = 0; ni < 8; ni++)
                mma8(s[ni], qf[ks], bq[ni >> 1][(ni & 1) * 2],
                     bq[ni >> 1][(ni & 1) * 2 + 1]);
        }

        // causal mask on diagonal-touching tiles
        if (kb >= 2 * qb) {
            int grow0 = qb * 128 + r0;
#pragma unroll
            for (int ni = 0; ni < 8; ni++) {
                int col = kb * 64 + ni * 8 + 2 * tig;
                if (col > grow0)         s[ni][0] = -1e30f;
                if (col + 1 > grow0)     s[ni][1] = -1e30f;
                if (col > grow0 + 8)     s[ni][2] = -1e30f;
                if (col + 1 > grow0 + 8) s[ni][3] = -1e30f;
            }
        }

        // online softmax (rows r0, r0+8; 4 lanes per row)
        float x0 = -1e30f, x1 = -1e30f;
#pragma unroll
        for (int ni = 0; ni < 8; ni++) {
            x0 = fmaxf(x0, fmaxf(s[ni][0], s[ni][1]));
            x1 = fmaxf(x1, fmaxf(s[ni][2], s[ni][3]));
        }
#pragma unroll
        for (int off = 1; off < 4; off <<= 1) {
            x0 = fmaxf(x0, __shfl_xor_sync(0xffffffffu, x0, off));
            x1 = fmaxf(x1, __shfl_xor_sync(0xffffffffu, x1, off));
        }
        float mn0 = fmaxf(m0, x0), mn1 = fmaxf(m1, x1);
        float corr0 = __expf(m0 - mn0), corr1 = __expf(m1 - mn1);
        m0 = mn0; m1 = mn1;

        float rs0 = 0.f, rs1 = 0.f;
#pragma unroll
        for (int ni = 0; ni < 8; ni++) {
            unsigned t0 = f2tf(__expf(s[ni][0] - m0));
            unsigned t1 = f2tf(__expf(s[ni][1] - m0));
            unsigned t2 = f2tf(__expf(s[ni][2] - m1));
            unsigned t3 = f2tf(__expf(s[ni][3] - m1));
            rs0 += __uint_as_float(t0) + __uint_as_float(t1);
            rs1 += __uint_as_float(t2) + __uint_as_float(t3);
            int col = ni * 8 + 2 * tig;
            unsigned w0 = (r0 * 64 + (col & 32) +
                           ((((col >> 2) & 7) ^ (r0 & 7)) << 2) + (col & 3)) << 2;
            unsigned w1 = ((r0 + 8) * 64 + (col & 32) +
                           ((((col >> 2) & 7) ^ ((r0 + 8) & 7)) << 2) + (col & 3)) << 2;
            *(uint2*)((char*)sm + w0) = make_uint2(t0, t1);
            *(uint2*)((char*)sm + w1) = make_uint2(t2, t3);
        }
#pragma unroll
        for (int off = 1; off < 4; off <<= 1) {
            rs0 += __shfl_xor_sync(0xffffffffu, rs0, off);
            rs1 += __shfl_xor_sync(0xffffffffu, rs1, off);
        }
        l0 = l0 * corr0 + rs0;
        l1 = l1 * corr1 + rs1;
#pragma unroll
        for (int ni = 0; ni < 8; ni++) {
            o[ni][0] *= corr0; o[ni][1] *= corr0;
            o[ni][2] *= corr1; o[ni][3] *= corr1;
        }
        __syncwarp();

        // O += P @ V  (P frags from QP rows; V frags rows = d)
#pragma unroll
        for (int ss = 0; ss < 8; ss++) {
            unsigned pa[4];
            ldsm4(pa, sQ + ((wq + ((ss & 4) << 3) +
                  ((((2 * ss) & 7) + shq ^ xq) << 2)) << 2));
            unsigned bq[4][4];
#pragma unroll
            for (int nj = 0; nj < 4; nj++)
                ldsm4(bq[nj], stV + ((wKB[nj] + ((ss & 4) << 3) +
                      ((((2 * ss) & 7) + shb ^ xKB[nj]) << 2)) << 2));
#pragma unroll
            for (int ni = 0; ni < 8; ni++)
                mma8(o[ni], pa, bq[ni >> 1][(ni & 1) * 2],
                     bq[ni >> 1][(ni & 1) * 2 + 1]);
        }
        __syncwarp();
    }

    // epilogue: normalize, write tf32 into g_ao head-concat layout
    float inv0 = 1.0f / l0, inv1 = 1.0f / l1;
    unsigned* Og = g_ao + ((size_t)b * Tn + (size_t)qb * 128 + r0) * HK + (size_t)h * Kd;
#pragma unroll
    for (int ni = 0; ni < 8; ni++) {
        int col = ni * 8 + 2 * tig;
        *(uint2*)(Og + col) =
            make_uint2(f2tf(o[ni][0] * inv0), f2tf(o[ni][1] * inv0));
        *(uint2*)(Og + 8 * HK + col) =
            make_uint2(f2tf(o[ni][2] * inv1), f2tf(o[ni][3] * inv1));
    }
}

// ---------------------------------------------------------------------------
extern "C" void kernel_launch(void* const* d_in, const int* in_sizes, int n_in,
                              void* d_out, int out_size)
{
    (void)in_sizes; (void)n_in; (void)out_size;
    const float* X  = (const float*)d_in[0];
    const float* Wq = (const float*)d_in[1];
    const float* Wk = (const float*)d_in[2];
    const float* Wv = (const float*)d_in[3];
    const float* Wo = (const float*)d_in[4];
    const float* bo = (const float*)d_in[5];
    float* Y = (float*)d_out;

    const int gemm_smem = 2 * 4096 * 4 * 2;                  // 64 KB
    const int attn_smem = (8192 + 2 * 4096 + 2 * 4096) * 4;  // 96 KB
    cudaFuncSetAttribute(qkv_mma,  cudaFuncAttributeMaxDynamicSharedMemorySize, gemm_smem);
    cudaFuncSetAttribute(proj_mma, cudaFuncAttributeMaxDynamicSharedMemorySize, gemm_smem);
    cudaFuncSetAttribute(attn_kernel, cudaFuncAttributeMaxDynamicSharedMemorySize, attn_smem);

    conv_kernel<<<8192, 256>>>((const float4*)X, (const float4*)Wo);
    gather_w<<<dim3(32, 48), 256>>>(Wq, Wk, Wv);
    qkv_mma<<<dim3(64, 24), 256, gemm_smem>>>();
    attn_kernel<<<dim3(Tn / 128, Bn * Hn), 256, attn_smem>>>();
    proj_mma<<<dim3(64, 8), 256, gemm_smem>>>(bo, Y);
}

// round 5
// speedup vs baseline: 5.2543x; 1.0693x over previous
#include <cuda_runtime.h>

// Problem constants
#define Bn 4
#define Tn 2048
#define Dn 1024
#define Hn 16
#define Kd 64
#define HK 1024

// q pre-scale: (1/sqrt(64)) * log2(e)  -> softmax done in base-2 domain
#define QSC 0.18033688011112042f

// ---- tf32 scratch (bit patterns stored as unsigned) ----
__device__ unsigned g_xt[Bn * Tn * Dn];          // X tf32 [8192][1024]
__device__ unsigned g_wall[3072 * 1024];         // gathered W^T tf32 [n][d]
__device__ unsigned g_wot[1024 * 1024];          // Wo tf32 [n][k]
__device__ unsigned g_q[Bn * Hn * Tn * Kd];      // tf32, pre-scaled [bh][t][d]
__device__ unsigned g_k[Bn * Hn * Tn * Kd];      // tf32 [bh][t][d]
__device__ unsigned g_vt[Bn * Hn * Kd * Tn];     // tf32 [bh][d][t]
__device__ unsigned g_ao[Bn * Tn * HK];          // tf32 [b*t][h*64+c]

__device__ __forceinline__ unsigned f2tf(float x) {
    unsigned r; asm("cvt.rna.tf32.f32 %0, %1;" : "=r"(r) : "f"(x)); return r;
}
__device__ __forceinline__ void mma8(float* c, const unsigned* a, unsigned b0, unsigned b1) {
    asm("mma.sync.aligned.m16n8k8.row.col.f32.tf32.tf32.f32 "
        "{%0,%1,%2,%3}, {%4,%5,%6,%7}, {%8,%9}, {%0,%1,%2,%3};"
        : "+f"(c[0]), "+f"(c[1]), "+f"(c[2]), "+f"(c[3])
        : "r"(a[0]), "r"(a[1]), "r"(a[2]), "r"(a[3]), "r"(b0), "r"(b1));
}
__device__ __forceinline__ void ldsm4(unsigned r[4], unsigned addr) {
    asm volatile("ldmatrix.sync.aligned.m8n8.x4.shared.b16 {%0,%1,%2,%3}, [%4];"
                 : "=r"(r[0]), "=r"(r[1]), "=r"(r[2]), "=r"(r[3]) : "r"(addr));
}
__device__ __forceinline__ void cpa16(unsigned d, const void* s) {
    asm volatile("cp.async.ca.shared.global [%0], [%1], 16;" :: "r"(d), "l"(s));
}
#define CP_COMMIT asm volatile("cp.async.commit_group;")
#define CP_WAIT0  asm volatile("cp.async.wait_group 0;")
__device__ __forceinline__ unsigned cvta_s(const void* p) {
    return (unsigned)__cvta_generic_to_shared(p);
}

// ---------------------------------------------------------------------------
// Prepass A: elementwise fp32->tf32 for X and Wo
// ---------------------------------------------------------------------------
__global__ __launch_bounds__(256) void conv_kernel(const float4* __restrict__ X,
                                                   const float4* __restrict__ Wo)
{
    int idx = blockIdx.x * 256 + threadIdx.x;
    float4 v = X[idx];
    uint4 o;
    o.x = f2tf(v.x); o.y = f2tf(v.y); o.z = f2tf(v.z); o.w = f2tf(v.w);
    *(uint4*)&g_xt[idx * 4] = o;
    if (idx < 262144) {
        float4 w = Wo[idx];
        uint4 ow;
        ow.x = f2tf(w.x); ow.y = f2tf(w.y); ow.z = f2tf(w.z); ow.w = f2tf(w.w);
        *(uint4*)&g_wot[idx * 4] = ow;
    }
}

// ---------------------------------------------------------------------------
// Prepass B: gather+transpose W{q,k,v}[h] (D x 64, k-major) -> g_wall[n][d]
// ---------------------------------------------------------------------------
__global__ __launch_bounds__(256) void gather_w(const float* __restrict__ Wq,
                                                const float* __restrict__ Wk,
                                                const float* __restrict__ Wv)
{
    __shared__ unsigned t[32][65];
    const int d0 = blockIdx.x * 32;
    const int wh = blockIdx.y;
    const int which = wh >> 4, h = wh & 15;
    const float* W = ((which == 0) ? Wq : (which == 1) ? Wk : Wv) + (size_t)h * Dn * Kd;
    const int tid = threadIdx.x;
#pragma unroll
    for (int i = 0; i < 8; i++) {
        int idx = tid + 256 * i;
        int dr = idx >> 6, c = idx & 63;
        t[dr][c] = f2tf(W[(size_t)(d0 + dr) * 64 + c]);
    }
    __syncthreads();
#pragma unroll
    for (int i = 0; i < 8; i++) {
        int idx = tid + 256 * i;
        int row = idx >> 5, dd = idx & 31;
        g_wall[(size_t)((which << 10) + (h << 6) + row) * 1024 + d0 + dd] = t[dd][row];
    }
}

// ---------------------------------------------------------------------------
// GEMM mainloop macro (unchanged from R4): 128x128 tile, cp.async dbl-buffer,
// ldmatrix fragments, XOR swizzle. 8 warps, warp tile 32m x 64n.
// ---------------------------------------------------------------------------
#define GEMM_MAIN(Aptr, Bptr, KTOT)                                              \
    const int tid = threadIdx.x;                                                 \
    const int w = tid >> 5, lane = tid & 31;                                     \
    const int g = lane >> 2, tig = lane & 3;                                     \
    const int wm = w >> 1, wn = w & 1;                                           \
    const int rl = lane & 7, sub = lane >> 3;                                    \
    const int shA = sub >> 1, shB = sub & 1;                                     \
    extern __shared__ unsigned sm[];                                             \
    const unsigned sA = cvta_s(sm);                                              \
    const unsigned sB = sA + 2 * 4096 * 4;                                       \
    const int r0f = tid >> 3, cf = tid & 7;                                      \
    const unsigned dA0 = sA + ((r0f * 32 + ((cf ^ (r0f & 7)) << 2)) << 2);       \
    const unsigned dB0 = sB + ((r0f * 32 + ((cf ^ (r0f & 7)) << 2)) << 2);       \
    int rowA0 = wm * 32 + ((sub & 1) << 3) + rl;                                 \
    int wA0 = rowA0 * 32, xA0 = rowA0 & 7;                                       \
    int wA1 = (rowA0 + 16) * 32, xA1 = (rowA0 + 16) & 7;                         \
    int rowB0 = wn * 64 + ((sub >> 1) << 3) + rl;                                \
    int wB[4], xB[4];                                                            \
    _Pragma("unroll") for (int nj = 0; nj < 4; nj++) {                           \
        int rb = rowB0 + nj * 16; wB[nj] = rb * 32; xB[nj] = rb & 7; }           \
    float acc[2][8][4];                                                          \
    _Pragma("unroll") for (int mi = 0; mi < 2; mi++)                             \
    _Pragma("unroll") for (int ni = 0; ni < 8; ni++)                             \
    _Pragma("unroll") for (int q = 0; q < 4; q++) acc[mi][ni][q] = 0.f;          \
    _Pragma("unroll") for (int i = 0; i < 4; i++) {                              \
        cpa16(dA0 + i * 4096, Aptr + (size_t)(r0f + 32 * i) * 1024 + cf * 4);    \
        cpa16(dB0 + i * 4096, Bptr + (size_t)(r0f + 32 * i) * 1024 + cf * 4); }  \
    CP_COMMIT;                                                                   \
    const int NIT = (KTOT) / 32;                                                 \
    for (int it = 0; it < NIT; it++) {                                           \
        CP_WAIT0; __syncthreads();                                               \
        int buf = it & 1;                                                        \
        if (it + 1 < NIT) {                                                      \
            int kk = (it + 1) * 32;                                              \
            unsigned off = (buf ^ 1) * 16384;                                    \
            _Pragma("unroll") for (int i = 0; i < 4; i++) {                      \
                cpa16(dA0 + off + i * 4096,                                      \
                      Aptr + (size_t)(r0f + 32 * i) * 1024 + kk + cf * 4);       \
                cpa16(dB0 + off + i * 4096,                                      \
                      Bptr + (size_t)(r0f + 32 * i) * 1024 + kk + cf * 4); }     \
            CP_COMMIT;                                                           \
        }                                                                        \
        unsigned stoff = buf * 16384;                                            \
        _Pragma("unroll") for (int ks = 0; ks < 4; ks++) {                       \
            unsigned a0[4], a1[4], bq[4][4];                                     \
            ldsm4(a0, sA + stoff + ((wA0 + (((2 * ks + shA) ^ xA0) << 2)) << 2));\
            ldsm4(a1, sA + stoff + ((wA1 + (((2 * ks + shA) ^ xA1) << 2)) << 2));\
            _Pragma("unroll") for (int nj = 0; nj < 4; nj++)                     \
                ldsm4(bq[nj], sB + stoff +                                       \
                      ((wB[nj] + (((2 * ks + shB) ^ xB[nj]) << 2)) << 2));       \
            _Pragma("unroll") for (int ni = 0; ni < 8; ni++) {                   \
                unsigned b0 = bq[ni >> 1][(ni & 1) * 2];                         \
                unsigned b1 = bq[ni >> 1][(ni & 1) * 2 + 1];                     \
                mma8(acc[0][ni], a0, b0, b1);                                    \
                mma8(acc[1][ni], a1, b0, b1);                                    \
            }                                                                    \
        }                                                                        \
    }

// ---------------------------------------------------------------------------
// Kernel 1: fused QKV GEMM; q pre-scaled by QSC (1/sqrt(K) * log2e)
// ---------------------------------------------------------------------------
__global__ __launch_bounds__(256, 2) void qkv_mma()
{
    const int mblk = blockIdx.x;
    const int nblk = blockIdx.y;
    const unsigned* Ag = g_xt + (size_t)mblk * 128 * Dn;
    const unsigned* Bg = g_wall + (size_t)nblk * 128 * 1024;

    GEMM_MAIN(Ag, Bg, 1024)

    const int which = nblk >> 3;
#pragma unroll
    for (int mi = 0; mi < 2; mi++) {
        int m = mblk * 128 + wm * 32 + mi * 16 + g;
        int b = m >> 11, t = m & 2047;
#pragma unroll
        for (int ni = 0; ni < 8; ni++) {
            int nl = nblk * 128 + wn * 64 + ni * 8 + 2 * tig;
            int hh = (nl >> 6) & 15, kcol = nl & 63;
            float c0 = acc[mi][ni][0], c1 = acc[mi][ni][1];
            float c2 = acc[mi][ni][2], c3 = acc[mi][ni][3];
            if (which == 0) {
                unsigned* p = g_q + ((size_t)(b * 16 + hh) * Tn + t) * 64 + kcol;
                *(uint2*)p = make_uint2(f2tf(c0 * QSC), f2tf(c1 * QSC));
                *(uint2*)(p + 8 * 64) = make_uint2(f2tf(c2 * QSC), f2tf(c3 * QSC));
            } else if (which == 1) {
                unsigned* p = g_k + ((size_t)(b * 16 + hh) * Tn + t) * 64 + kcol;
                *(uint2*)p = make_uint2(f2tf(c0), f2tf(c1));
                *(uint2*)(p + 8 * 64) = make_uint2(f2tf(c2), f2tf(c3));
            } else {
                unsigned* p = g_vt + ((size_t)(b * 16 + hh) * 64 + kcol) * Tn + t;
                p[0] = f2tf(c0); p[Tn] = f2tf(c1);
                p[8] = f2tf(c2); p[Tn + 8] = f2tf(c3);
            }
        }
    }
}

// ---------------------------------------------------------------------------
// Kernel 3: output projection
// ---------------------------------------------------------------------------
__global__ __launch_bounds__(256, 2) void proj_mma(const float* __restrict__ bo,
                                                   float* __restrict__ Y)
{
    const int mblk = blockIdx.x;
    const int nblk = blockIdx.y;
    const unsigned* Ag = g_ao + (size_t)mblk * 128 * HK;
    const unsigned* Bg = g_wot + (size_t)nblk * 128 * 1024;

    GEMM_MAIN(Ag, Bg, 1024)

#pragma unroll
    for (int mi = 0; mi < 2; mi++) {
        int m = mblk * 128 + wm * 32 + mi * 16 + g;
#pragma unroll
        for (int ni = 0; ni < 8; ni++) {
            int n = nblk * 128 + wn * 64 + ni * 8 + 2 * tig;
            float2 bb = *(const float2*)(bo + n);
            *(float2*)(Y + (size_t)m * HK + n) =
                make_float2(acc[mi][ni][0] + bb.x, acc[mi][ni][1] + bb.y);
            *(float2*)(Y + (size_t)(m + 8) * HK + n) =
                make_float2(acc[mi][ni][2] + bb.x, acc[mi][ni][3] + bb.y);
        }
    }
}

// ---------------------------------------------------------------------------
// Kernel 2: causal flash attention. 128 threads = 4 warps, warp owns 32 q-rows
// (2 A-fragment groups) -> B fragments (K, V) amortized over 2x the mma work.
// smem: Q/P 128x64, K 2x64x64, V 2x64x64 (64-word swizzled rows).  96 KB.
// ---------------------------------------------------------------------------
__global__ __launch_bounds__(128, 2) void attn_kernel()
{
    extern __shared__ unsigned sm[];
    const unsigned sQ = cvta_s(sm);
    const unsigned sK = sQ + 8192 * 4;
    const unsigned sV = sK + 2 * 4096 * 4;

    const int qb = (int)gridDim.x - 1 - (int)blockIdx.x;  // big tiles first
    const int bh = blockIdx.y;
    const int b = bh >> 4, h = bh & 15;

    const int tid = threadIdx.x;
    const int w = tid >> 5, lane = tid & 31;
    const int g = lane >> 2, tig = lane & 3;
    const int rl = lane & 7, sub = lane >> 3;
    const int shq = sub >> 1, shb = sub & 1;

    const unsigned* Qg = g_q + ((size_t)bh * Tn + (size_t)qb * 128) * 64;
    const unsigned* Kg = g_k + (size_t)bh * Tn * 64;
    const unsigned* Vt = g_vt + (size_t)bh * 64 * Tn;

    // fill mapping (64-word rows, 8-row stride keeps row&7 constant)
    const int frow = tid >> 4, fc = tid & 15;
    const unsigned foff = ((frow * 64 + ((fc >> 3) << 5) +
                            (((fc & 7) ^ (frow & 7)) << 2)) << 2);

    // prefetch Q (128 rows) + K0 + V0 (64 rows each)
#pragma unroll
    for (int i = 0; i < 16; i++)
        cpa16(sQ + foff + i * 2048, Qg + (size_t)(frow + 8 * i) * 64 + fc * 4);
#pragma unroll
    for (int i = 0; i < 8; i++) {
        cpa16(sK + foff + i * 2048, Kg + (size_t)(frow + 8 * i) * 64 + fc * 4);
        cpa16(sV + foff + i * 2048, Vt + (size_t)(frow + 8 * i) * Tn + fc * 4);
    }
    CP_COMMIT;
    CP_WAIT0;
    __syncthreads();

    // extract Q fragments for rows w*32 .. w*32+31 (2 x 16-row groups)
    unsigned qf[8][2][4];
    int wqm[2], xqm[2];
#pragma unroll
    for (int mi = 0; mi < 2; mi++) {
        int rowQ = w * 32 + mi * 16 + ((sub & 1) << 3) + rl;
        wqm[mi] = rowQ * 64; xqm[mi] = rowQ & 7;
#pragma unroll
        for (int ks = 0; ks < 8; ks++)
            ldsm4(qf[ks][mi], sQ + ((wqm[mi] + ((ks & 4) << 3) +
                  ((((2 * ks) & 7) + shq ^ xqm[mi]) << 2)) << 2));
    }
    // Q rows now warp-private P storage (no cross-warp access -> no syncthreads)

    // B-fragment lane constants (shared by K rows and V rows)
    int rowB0 = ((sub >> 1) << 3) + rl;
    int wKB[4], xKB[4];
#pragma unroll
    for (int nj = 0; nj < 4; nj++) {
        int rb = rowB0 + nj * 16; wKB[nj] = rb * 64; xKB[nj] = rb & 7;
    }

    float mrow[4], lrow[4];   // index = mi*2 + half
    float o[2][8][4];
#pragma unroll
    for (int q = 0; q < 4; q++) { mrow[q] = -1e30f; lrow[q] = 0.f; }
#pragma unroll
    for (int mi = 0; mi < 2; mi++)
#pragma unroll
        for (int ni = 0; ni < 8; ni++)
#pragma unroll
            for (int q = 0; q < 4; q++) o[mi][ni][q] = 0.f;

    const int kbmax = 2 * qb + 1;

    for (int kb = 0; kb <= kbmax; kb++) {
        const int buf = kb & 1;
        if (kb) { CP_WAIT0; __syncthreads(); }
        if (kb < kbmax) {
            unsigned off = (buf ^ 1) * 16384;
            int s0g = (kb + 1) * 64;
#pragma unroll
            for (int i = 0; i < 8; i++) {
                cpa16(sK + off + foff + i * 2048,
                      Kg + (size_t)(s0g + frow + 8 * i) * 64 + fc * 4);
                cpa16(sV + off + foff + i * 2048,
                      Vt + (size_t)(frow + 8 * i) * Tn + s0g + fc * 4);
            }
            CP_COMMIT;
        }
        const unsigned stK = sK + buf * 16384;
        const unsigned stV = sV + buf * 16384;

        // S = Q @ K^T  (32 rows x 64 cols per warp)
        float s[2][8][4];
#pragma unroll
        for (int mi = 0; mi < 2; mi++)
#pragma unroll
            for (int ni = 0; ni < 8; ni++)
#pragma unroll
                for (int q = 0; q < 4; q++) s[mi][ni][q] = 0.f;
#pragma unroll
        for (int ks = 0; ks < 8; ks++) {
            unsigned bq[4][4];
#pragma unroll
            for (int nj = 0; nj < 4; nj++)
                ldsm4(bq[nj], stK + ((wKB[nj] + ((ks & 4) << 3) +
                      ((((2 * ks) & 7) + shb ^ xKB[nj]) << 2)) << 2));
#pragma unroll
            for (int ni = 0; ni < 8; ni++) {
                unsigned b0 = bq[ni >> 1][(ni & 1) * 2];
                unsigned b1 = bq[ni >> 1][(ni & 1) * 2 + 1];
                mma8(s[0][ni], qf[ks][0], b0, b1);
                mma8(s[1][ni], qf[ks][1], b0, b1);
            }
        }

        // causal mask (diagonal-touching tiles only)
        if (kb >= 2 * qb) {
#pragma unroll
            for (int mi = 0; mi < 2; mi++) {
                int grow0 = qb * 128 + w * 32 + mi * 16 + g;
#pragma unroll
                for (int ni = 0; ni < 8; ni++) {
                    int col = kb * 64 + ni * 8 + 2 * tig;
                    if (col > grow0)         s[mi][ni][0] = -1e30f;
                    if (col + 1 > grow0)     s[mi][ni][1] = -1e30f;
                    if (col > grow0 + 8)     s[mi][ni][2] = -1e30f;
                    if (col + 1 > grow0 + 8) s[mi][ni][3] = -1e30f;
                }
            }
        }

        // online softmax in base-2 domain (q pre-scaled by log2e/sqrt(K))
#pragma unroll
        for (int mi = 0; mi < 2; mi++) {
            float x0 = -1e30f, x1 = -1e30f;
#pragma unroll
            for (int ni = 0; ni < 8; ni++) {
                x0 = fmaxf(x0, fmaxf(s[mi][ni][0], s[mi][ni][1]));
                x1 = fmaxf(x1, fmaxf(s[mi][ni][2], s[mi][ni][3]));
            }
#pragma unroll
            for (int off = 1; off < 4; off <<= 1) {
                x0 = fmaxf(x0, __shfl_xor_sync(0xffffffffu, x0, off));
                x1 = fmaxf(x1, __shfl_xor_sync(0xffffffffu, x1, off));
            }
            float m0 = mrow[mi * 2], m1 = mrow[mi * 2 + 1];
            float mn0 = fmaxf(m0, x0), mn1 = fmaxf(m1, x1);
            float corr0 = exp2f(m0 - mn0), corr1 = exp2f(m1 - mn1);
            mrow[mi * 2] = mn0; mrow[mi * 2 + 1] = mn1;

            int rr0 = w * 32 + mi * 16 + g;
            int rr1 = rr0 + 8;
            float rs0 = 0.f, rs1 = 0.f;
#pragma unroll
            for (int ni = 0; ni < 8; ni++) {
                unsigned t0 = f2tf(exp2f(s[mi][ni][0] - mn0));
                unsigned t1 = f2tf(exp2f(s[mi][ni][1] - mn0));
                unsigned t2 = f2tf(exp2f(s[mi][ni][2] - mn1));
                unsigned t3 = f2tf(exp2f(s[mi][ni][3] - mn1));
                rs0 += __uint_as_float(t0) + __uint_as_float(t1);
                rs1 += __uint_as_float(t2) + __uint_as_float(t3);
                int col = ni * 8 + 2 * tig;
                unsigned w0 = (rr0 * 64 + (col & 32) +
                               ((((col >> 2) & 7) ^ (rr0 & 7)) << 2) + (col & 3)) << 2;
                unsigned w1 = (rr1 * 64 + (col & 32) +
                               ((((col >> 2) & 7) ^ (rr1 & 7)) << 2) + (col & 3)) << 2;
                *(uint2*)((char*)sm + w0) = make_uint2(t0, t1);
                *(uint2*)((char*)sm + w1) = make_uint2(t2, t3);
            }
#pragma unroll
            for (int off = 1; off < 4; off <<= 1) {
                rs0 += __shfl_xor_sync(0xffffffffu, rs0, off);
                rs1 += __shfl_xor_sync(0xffffffffu, rs1, off);
            }
            lrow[mi * 2] = lrow[mi * 2] * corr0 + rs0;
            lrow[mi * 2 + 1] = lrow[mi * 2 + 1] * corr1 + rs1;
#pragma unroll
            for (int ni = 0; ni < 8; ni++) {
                o[mi][ni][0] *= corr0; o[mi][ni][1] *= corr0;
                o[mi][ni][2] *= corr1; o[mi][ni][3] *= corr1;
            }
        }
        __syncwarp();

        // O += P @ V
#pragma unroll
        for (int ss = 0; ss < 8; ss++) {
            unsigned pa[2][4];
#pragma unroll
            for (int mi = 0; mi < 2; mi++)
                ldsm4(pa[mi], sQ + ((wqm[mi] + ((ss & 4) << 3) +
                      ((((2 * ss) & 7) + shq ^ xqm[mi]) << 2)) << 2));
            unsigned bq[4][4];
#pragma unroll
            for (int nj = 0; nj < 4; nj++)
                ldsm4(bq[nj], stV + ((wKB[nj] + ((ss & 4) << 3) +
                      ((((2 * ss) & 7) + shb ^ xKB[nj]) << 2)) << 2));
#pragma unroll
            for (int ni = 0; ni < 8; ni++) {
                unsigned b0 = bq[ni >> 1][(ni & 1) * 2];
                unsigned b1 = bq[ni >> 1][(ni & 1) * 2 + 1];
                mma8(o[0][ni], pa[0], b0, b1);
                mma8(o[1][ni], pa[1], b0, b1);
            }
        }
        __syncwarp();
    }

    // epilogue: normalize, write tf32 into g_ao head-concat layout
#pragma unroll
    for (int mi = 0; mi < 2; mi++) {
        float inv0 = 1.0f / lrow[mi * 2], inv1 = 1.0f / lrow[mi * 2 + 1];
        int rr = qb * 128 + w * 32 + mi * 16 + g;
        unsigned* Og = g_ao + ((size_t)b * Tn + rr) * HK + (size_t)h * Kd;
#pragma unroll
        for (int ni = 0; ni < 8; ni++) {
            int col = ni * 8 + 2 * tig;
            *(uint2*)(Og + col) =
                make_uint2(f2tf(o[mi][ni][0] * inv0), f2tf(o[mi][ni][1] * inv0));
            *(uint2*)(Og + 8 * HK + col) =
                make_uint2(f2tf(o[mi][ni][2] * inv1), f2tf(o[mi][ni][3] * inv1));
        }
    }
}

// ---------------------------------------------------------------------------
extern "C" void kernel_launch(void* const* d_in, const int* in_sizes, int n_in,
                              void* d_out, int out_size)
{
    (void)in_sizes; (void)n_in; (void)out_size;
    const float* X  = (const float*)d_in[0];
    const float* Wq = (const float*)d_in[1];
    const float* Wk = (const float*)d_in[2];
    const float* Wv = (const float*)d_in[3];
    const float* Wo = (const float*)d_in[4];
    const float* bo = (const float*)d_in[5];
    float* Y = (float*)d_out;

    const int gemm_smem = 2 * 4096 * 4 * 2;                  // 64 KB
    const int attn_smem = (8192 + 2 * 4096 + 2 * 4096) * 4;  // 96 KB
    cudaFuncSetAttribute(qkv_mma,  cudaFuncAttributeMaxDynamicSharedMemorySize, gemm_smem);
    cudaFuncSetAttribute(proj_mma, cudaFuncAttributeMaxDynamicSharedMemorySize, gemm_smem);
    cudaFuncSetAttribute(attn_kernel, cudaFuncAttributeMaxDynamicSharedMemorySize, attn_smem);

    conv_kernel<<<8192, 256>>>((const float4*)X, (const float4*)Wo);
    gather_w<<<dim3(32, 48), 256>>>(Wq, Wk, Wv);
    qkv_mma<<<dim3(64, 24), 256, gemm_smem>>>();
    attn_kernel<<<dim3(Tn / 128, Bn * Hn), 128, attn_smem>>>();
    proj_mma<<<dim3(64, 8), 256, gemm_smem>>>(bo, Y);
}